// round 3
// baseline (speedup 1.0000x reference)
#include <cuda_runtime.h>
#include <cstdint>

#define B_ 4
#define C_ 3
#define T_ 103
#define H_ 224
#define W_ 224
#define HW_ (H_ * W_)
#define W4_ (W_ / 4)        // 56 float4 per row
#define ROWS_PER_BLK 16
#define NIMG (B_ * C_ * T_) // 1236

// Predicated 128-bit load: returns loaded value if pred, else zeros.
// No branch -> no BSSY/BSYNC, batchable by ptxas.
__device__ __forceinline__ float4 ldg128_pred(const float* p, int pred) {
    float4 v = make_float4(0.f, 0.f, 0.f, 0.f);
    asm volatile("{\n\t"
                 ".reg .pred lp;\n\t"
                 "setp.ne.b32 lp, %4, 0;\n\t"
                 "@lp ld.global.nc.v4.f32 {%0,%1,%2,%3}, [%5];\n\t"
                 "}"
                 : "+f"(v.x), "+f"(v.y), "+f"(v.z), "+f"(v.w)
                 : "r"(pred), "l"(p));
    return v;
}

__global__ __launch_bounds__(224)
void fuse_kernel(const float* __restrict__ video,
                 const float* __restrict__ bbox,
                 const int* __restrict__ index,
                 float* __restrict__ out)
{
    const int bct = blockIdx.y;              // (b*C + c)*T + t
    const int b   = bct / (C_ * T_);
    const int t   = bct % T_;

    __shared__ int s_cx0, s_cx1, s_cy0, s_cy1;   // own clamped mask rect
    __shared__ int s_bx0, s_bx1, s_by0, s_by1;   // perm br rect (unclamped ints)
    __shared__ int s_bp;

    if (threadIdx.x == 0 && threadIdx.y == 0) {
        const int bp = index[b];
        s_bp = bp;

        const float* bb = bbox + ((size_t)b * T_ + t) * 8;
        float xmin = fminf(fminf(bb[0], bb[2]), fminf(bb[4], bb[6]));
        float xmax = fmaxf(fmaxf(bb[0], bb[2]), fmaxf(bb[4], bb[6]));
        float ymin = fminf(fminf(bb[1], bb[3]), fminf(bb[5], bb[7]));
        float ymax = fmaxf(fmaxf(bb[1], bb[3]), fmaxf(bb[5], bb[7]));
        s_cx0 = (int)fmaxf(xmin, 0.0f);
        s_cy0 = (int)fmaxf(ymin, 0.0f);
        s_cx1 = (int)fminf(xmax, (float)W_);
        s_cy1 = (int)fminf(ymax, (float)H_);

        const float* bbp = bbox + ((size_t)bp * T_ + t) * 8;
        s_bx0 = (int)fminf(fminf(bbp[0], bbp[2]), fminf(bbp[4], bbp[6]));
        s_bx1 = (int)fmaxf(fmaxf(bbp[0], bbp[2]), fmaxf(bbp[4], bbp[6]));
        s_by0 = (int)fminf(fminf(bbp[1], bbp[3]), fminf(bbp[5], bbp[7]));
        s_by1 = (int)fmaxf(fmaxf(bbp[1], bbp[3]), fmaxf(bbp[5], bbp[7]));
    }
    __syncthreads();

    const int cx0 = s_cx0, cx1 = s_cx1, cy0 = s_cy0, cy1 = s_cy1;
    const int bx0 = s_bx0, bx1 = s_bx1, by0 = s_by0, by1 = s_by1;
    const int bp  = s_bp;

    const int x  = threadIdx.x * 4;                      // pixel column of chunk
    const int h0 = blockIdx.x * ROWS_PER_BLK + threadIdx.y;

    // x-side classification (loop-invariant across the 4 rows)
    bool mx[4], brx[4];
#pragma unroll
    for (int i = 0; i < 4; i++) {
        const int xi = x + i;
        mx[i]  = (xi >= cx0) & (xi <= cx1);
        brx[i] = (xi >= bx0) & (xi <= bx1);
    }
    const bool mAnyX = mx[0] | mx[1] | mx[2] | mx[3];

    const int c = (bct / T_) % C_;
    const size_t base = (size_t)h0 * W_ + x;
    const float* ownP  = video + (size_t)bct * HW_ + base;
    const float* permP = video + (((size_t)bp * C_ + c) * T_ + t) * (size_t)HW_ + base;
    float*       outP  = out + (size_t)bct * HW_ + base;
    const int rowStride4 = 4 * W_;   // elements between processed rows

    // Per-row predicates (all 4 rows up front)
    bool m[4][4], bg[4][4];
    int needOwn[4], needPerm[4];
#pragma unroll
    for (int j = 0; j < 4; j++) {
        const int h = h0 + 4 * j;
        const bool rowM  = (h >= cy0) & (h <= cy1);
        const bool rowBr = (h >= by0) & (h <= by1);
        bool anyBg = false;
#pragma unroll
        for (int i = 0; i < 4; i++) {
            m[j][i]  = rowM & mx[i];
            bg[j][i] = !((rowBr & brx[i]) | m[j][i]);
            anyBg |= bg[j][i];
        }
        needOwn[j]  = (rowM & mAnyX) ? 1 : 0;
        needPerm[j] = anyBg ? 1 : 0;
    }

    // Front-batched predicated loads: up to 8 LDG.128 in flight.
    float4 ownv[4], permv[4];
#pragma unroll
    for (int j = 0; j < 4; j++)
        ownv[j]  = ldg128_pred(ownP  + j * rowStride4, needOwn[j]);
#pragma unroll
    for (int j = 0; j < 4; j++)
        permv[j] = ldg128_pred(permP + j * rowStride4, needPerm[j]);

    // Select + store
#pragma unroll
    for (int j = 0; j < 4; j++) {
        float4 r;
        r.x = m[j][0] ? ownv[j].x : (bg[j][0] ? permv[j].x : 0.0f);
        r.y = m[j][1] ? ownv[j].y : (bg[j][1] ? permv[j].y : 0.0f);
        r.z = m[j][2] ? ownv[j].z : (bg[j][2] ? permv[j].z : 0.0f);
        r.w = m[j][3] ? ownv[j].w : (bg[j][3] ? permv[j].w : 0.0f);
        *reinterpret_cast<float4*>(outP + j * rowStride4) = r;
    }
}

extern "C" void kernel_launch(void* const* d_in, const int* in_sizes, int n_in,
                              void* d_out, int out_size)
{
    const float* video = (const float*)d_in[0];
    const float* bbox  = (const float*)d_in[1];
    const int*   index = (const int*)d_in[2];
    float* out = (float*)d_out;

    dim3 block(W4_, 4);                    // 224 threads
    dim3 grid(H_ / ROWS_PER_BLK, NIMG);    // (14, 1236)
    fuse_kernel<<<grid, block>>>(video, bbox, index, out);
}

// round 4
// speedup vs baseline: 1.0659x; 1.0659x over previous
#include <cuda_runtime.h>
#include <cstdint>

#define B_ 4
#define C_ 3
#define T_ 103
#define H_ 224
#define W_ 224
#define HW_ (H_ * W_)
#define W4_ (W_ / 4)          // 56 float4 per row
#define HALF_H (H_ / 2)       // 112
#define TPB 224
#define CHUNKS_HALF (W4_ * HALF_H)   // 6272 chunks in half-image
#define NBLK_X (CHUNKS_HALF / TPB)   // 28
#define NIMG (B_ * C_ * T_)          // 1236

// Predicated 128-bit load: value if pred, else zeros. No branch.
__device__ __forceinline__ float4 ldg128_pred(const float* p, int pred) {
    float4 v = make_float4(0.f, 0.f, 0.f, 0.f);
    asm volatile("{\n\t"
                 ".reg .pred lp;\n\t"
                 "setp.ne.b32 lp, %4, 0;\n\t"
                 "@lp ld.global.nc.v4.f32 {%0,%1,%2,%3}, [%5];\n\t"
                 "}"
                 : "+f"(v.x), "+f"(v.y), "+f"(v.z), "+f"(v.w)
                 : "r"(pred), "l"(p));
    return v;
}

__global__ __launch_bounds__(TPB)
void fuse_kernel(const float* __restrict__ video,
                 const float* __restrict__ bbox,
                 const int* __restrict__ index,
                 float* __restrict__ out)
{
    const int bct = blockIdx.y;              // (b*C + c)*T + t
    const int b   = bct / (C_ * T_);
    const int t   = bct % T_;

    __shared__ int s_cx0, s_cx1, s_cy0, s_cy1;
    __shared__ int s_bx0, s_bx1, s_by0, s_by1;
    __shared__ int s_bp;

    if (threadIdx.x == 0) {
        const int bp = index[b];
        s_bp = bp;
        const float* bb = bbox + ((size_t)b * T_ + t) * 8;
        float xmin = fminf(fminf(bb[0], bb[2]), fminf(bb[4], bb[6]));
        float xmax = fmaxf(fmaxf(bb[0], bb[2]), fmaxf(bb[4], bb[6]));
        float ymin = fminf(fminf(bb[1], bb[3]), fminf(bb[5], bb[7]));
        float ymax = fmaxf(fmaxf(bb[1], bb[3]), fmaxf(bb[5], bb[7]));
        s_cx0 = (int)fmaxf(xmin, 0.0f);
        s_cy0 = (int)fmaxf(ymin, 0.0f);
        s_cx1 = (int)fminf(xmax, (float)W_);
        s_cy1 = (int)fminf(ymax, (float)H_);
        const float* bbp = bbox + ((size_t)bp * T_ + t) * 8;
        s_bx0 = (int)fminf(fminf(bbp[0], bbp[2]), fminf(bbp[4], bbp[6]));
        s_bx1 = (int)fmaxf(fmaxf(bbp[0], bbp[2]), fmaxf(bbp[4], bbp[6]));
        s_by0 = (int)fminf(fminf(bbp[1], bbp[3]), fminf(bbp[5], bbp[7]));
        s_by1 = (int)fmaxf(fmaxf(bbp[1], bbp[3]), fmaxf(bbp[5], bbp[7]));
    }
    __syncthreads();

    const int cx0 = s_cx0, cx1 = s_cx1, cy0 = s_cy0, cy1 = s_cy1;
    const int bx0 = s_bx0, bx1 = s_bx1, by0 = s_by0, by1 = s_by1;
    const int bp  = s_bp;

    const int p  = blockIdx.x * TPB + threadIdx.x;   // chunk in half-image
    const int h0 = p / W4_;                          // row 0..111
    const int x  = (p % W4_) * 4;                    // pixel column

    // x-side classification, once per thread
    float fmx[4], fbx[4];
    bool mAnyX = false, mAllX = true, brAllX = true, covMB = true;
#pragma unroll
    for (int i = 0; i < 4; i++) {
        const int xi = x + i;
        const bool mi  = (xi >= cx0) & (xi <= cx1);
        const bool bri = (xi >= bx0) & (xi <= bx1);
        fmx[i] = mi  ? 1.0f : 0.0f;
        fbx[i] = bri ? 1.0f : 0.0f;
        mAnyX  |= mi;
        mAllX  &= mi;
        brAllX &= bri;
        covMB  &= (mi | bri);
    }

    const int c = (bct / T_) % C_;
    const size_t base = (size_t)h0 * W_ + x;
    const float* ownP  = video + (size_t)bct * HW_ + base;
    const float* permP = video + (((size_t)bp * C_ + c) * T_ + t) * (size_t)HW_ + base;
    float*       outP  = out + (size_t)bct * HW_ + base;
    const int halfStride = HALF_H * W_;   // elements between the 2 rows

#pragma unroll
    for (int j = 0; j < 2; j++) {
        const int h = h0 + HALF_H * j;
        const bool rowM  = (h >= cy0) & (h <= cy1);
        const bool rowBr = (h >= by0) & (h <= by1);

        const int needOwn = (rowM & mAnyX) ? 1 : 0;
        const bool covAll = rowM ? (rowBr ? covMB : mAllX)
                                 : (rowBr ? brAllX : false);
        const int needPerm = covAll ? 0 : 1;

        const float frM = rowM  ? 1.0f : 0.0f;
        const float frB = rowBr ? 1.0f : 0.0f;

        const float4 own  = ldg128_pred(ownP  + j * halfStride, needOwn);
        const float4 perm = ldg128_pred(permP + j * halfStride, needPerm);

        float4 r;
        {
            // per element: fm = frM*fmx; a = 1 - frB*fbx; u = (1-fm)*a
            // r = own*fm + perm*u     (all on fma pipe, exact for 0/1 masks)
            float fm, a, u;
            fm = frM * fmx[0]; a = fmaf(-frB, fbx[0], 1.0f); u = fmaf(-fm, a, a);
            r.x = fmaf(perm.x, u, own.x * fm);
            fm = frM * fmx[1]; a = fmaf(-frB, fbx[1], 1.0f); u = fmaf(-fm, a, a);
            r.y = fmaf(perm.y, u, own.y * fm);
            fm = frM * fmx[2]; a = fmaf(-frB, fbx[2], 1.0f); u = fmaf(-fm, a, a);
            r.z = fmaf(perm.z, u, own.z * fm);
            fm = frM * fmx[3]; a = fmaf(-frB, fbx[3], 1.0f); u = fmaf(-fm, a, a);
            r.w = fmaf(perm.w, u, own.w * fm);
        }
        *reinterpret_cast<float4*>(outP + j * halfStride) = r;
    }
}

extern "C" void kernel_launch(void* const* d_in, const int* in_sizes, int n_in,
                              void* d_out, int out_size)
{
    const float* video = (const float*)d_in[0];
    const float* bbox  = (const float*)d_in[1];
    const int*   index = (const int*)d_in[2];
    float* out = (float*)d_out;

    dim3 grid(NBLK_X, NIMG);   // (28, 1236)
    fuse_kernel<<<grid, TPB>>>(video, bbox, index, out);
}

// round 6
// speedup vs baseline: 1.1433x; 1.0726x over previous
#include <cuda_runtime.h>
#include <cstdint>

#define B_ 4
#define C_ 3
#define T_ 103
#define H_ 224
#define W_ 224
#define HW_ (H_ * W_)
#define W4_ (W_ / 4)          // 56 float4 per row
#define NBT (B_ * T_)         // 412

// Predicated 128-bit load: value if pred, else zeros. No branch.
__device__ __forceinline__ float4 ldg128_pred(const float* p, int pred) {
    float4 v = make_float4(0.f, 0.f, 0.f, 0.f);
    asm volatile("{\n\t"
                 ".reg .pred lp;\n\t"
                 "setp.ne.b32 lp, %4, 0;\n\t"
                 "@lp ld.global.nc.v4.f32 {%0,%1,%2,%3}, [%5];\n\t"
                 "}"
                 : "+f"(v.x), "+f"(v.y), "+f"(v.z), "+f"(v.w)
                 : "r"(pred), "l"(p));
    return v;
}

__global__ __launch_bounds__(224)
void fuse_kernel(const float* __restrict__ video,
                 const float* __restrict__ bbox,
                 const int* __restrict__ index,
                 float* __restrict__ out)
{
    const int bt = blockIdx.y;               // b*T + t
    const int b  = bt / T_;
    const int t  = bt % T_;

    __shared__ int s_cx0, s_cxr, s_cy0, s_cyr;   // own rect: lo + range
    __shared__ int s_bx0, s_bxr, s_by0, s_byr;   // perm br rect: lo + range
    __shared__ int s_bp;

    if (threadIdx.x == 0 && threadIdx.y == 0) {
        const int bp = index[b];
        s_bp = bp;
        const float* bb = bbox + ((size_t)b * T_ + t) * 8;
        float xmin = fminf(fminf(bb[0], bb[2]), fminf(bb[4], bb[6]));
        float xmax = fmaxf(fmaxf(bb[0], bb[2]), fmaxf(bb[4], bb[6]));
        float ymin = fminf(fminf(bb[1], bb[3]), fminf(bb[5], bb[7]));
        float ymax = fmaxf(fmaxf(bb[1], bb[3]), fmaxf(bb[5], bb[7]));
        const int cx0 = (int)fmaxf(xmin, 0.0f);
        const int cy0 = (int)fmaxf(ymin, 0.0f);
        const int cx1 = (int)fminf(xmax, (float)W_);
        const int cy1 = (int)fminf(ymax, (float)H_);
        s_cx0 = cx0; s_cxr = cx1 - cx0;
        s_cy0 = cy0; s_cyr = cy1 - cy0;

        const float* bbp = bbox + ((size_t)bp * T_ + t) * 8;
        const int bx0 = (int)fminf(fminf(bbp[0], bbp[2]), fminf(bbp[4], bbp[6]));
        const int bx1 = (int)fmaxf(fmaxf(bbp[0], bbp[2]), fmaxf(bbp[4], bbp[6]));
        const int by0 = (int)fminf(fminf(bbp[1], bbp[3]), fminf(bbp[5], bbp[7]));
        const int by1 = (int)fmaxf(fmaxf(bbp[1], bbp[3]), fmaxf(bbp[5], bbp[7]));
        s_bx0 = bx0; s_bxr = bx1 - bx0;
        s_by0 = by0; s_byr = by1 - by0;
    }
    __syncthreads();

    const int h = blockIdx.x * 4 + threadIdx.y;   // row 0..223
    const int x = threadIdx.x * 4;                // pixel column

    // Row classification (1 compare each via unsigned-range trick)
    const bool rowM  = (unsigned)(h - s_cy0) <= (unsigned)s_cyr;
    const bool rowBr = (unsigned)(h - s_by0) <= (unsigned)s_byr;
    const float frB  = rowBr ? 1.0f : 0.0f;

    // Per-element blend coefficients, computed ONCE, reused for 3 channels.
    // fm[i] = inside own mask; u[i] = background weight; r = own*fm + perm*u
    float fm[4], u[4];
    bool anyM = false, anyBg = false;
#pragma unroll
    for (int i = 0; i < 4; i++) {
        const int xi = x + i;
        const bool mi  = rowM  & ((unsigned)(xi - s_cx0) <= (unsigned)s_cxr);
        const bool bri = (unsigned)(xi - s_bx0) <= (unsigned)s_bxr;
        fm[i] = mi ? 1.0f : 0.0f;
        const float a = fmaf(-frB, bri ? 1.0f : 0.0f, 1.0f);  // 1 - frB*fbx
        u[i] = fmaf(-fm[i], a, a);                            // (1-fm)*a
        anyM  |= mi;
        anyBg |= (u[i] != 0.0f);
    }
    const int needOwn  = anyM  ? 1 : 0;
    const int needPerm = anyBg ? 1 : 0;

    // Base pointers for channel 0; channel stride = T*H*W elements.
    const size_t rowOff = (size_t)h * W_ + x;
    const size_t cs     = (size_t)T_ * HW_;
    const float* ownP  = video + ((size_t)(b * C_) * T_ + t) * (size_t)HW_ + rowOff;
    const float* permP = video + ((size_t)(s_bp * C_) * T_ + t) * (size_t)HW_ + rowOff;
    float*       outP  = out   + ((size_t)(b * C_) * T_ + t) * (size_t)HW_ + rowOff;

#pragma unroll
    for (int c = 0; c < C_; c++) {
        const float4 own  = ldg128_pred(ownP,  needOwn);
        const float4 perm = ldg128_pred(permP, needPerm);
        float4 r;
        r.x = fmaf(own.x, fm[0], perm.x * u[0]);
        r.y = fmaf(own.y, fm[1], perm.y * u[1]);
        r.z = fmaf(own.z, fm[2], perm.z * u[2]);
        r.w = fmaf(own.w, fm[3], perm.w * u[3]);
        *reinterpret_cast<float4*>(outP) = r;
        ownP  += cs;
        permP += cs;
        outP  += cs;
    }
}

extern "C" void kernel_launch(void* const* d_in, const int* in_sizes, int n_in,
                              void* d_out, int out_size)
{
    const float* video = (const float*)d_in[0];
    const float* bbox  = (const float*)d_in[1];
    const int*   index = (const int*)d_in[2];
    float* out = (float*)d_out;

    dim3 block(W4_, 4);          // 224 threads
    dim3 grid(H_ / 4, NBT);      // (56, 412)
    fuse_kernel<<<grid, block>>>(video, bbox, index, out);
}